// round 2
// baseline (speedup 1.0000x reference)
#include <cuda_runtime.h>
#include <math.h>

#define B_    64
#define F_    1024
#define HID_  2048
#define NH_   4
#define KS_   4
#define BS_   4
#define HD_   512
#define NB_   512
#define EPS_  1e-6f
#define KSC   0.044194173824159216f   // 1/sqrt(512)

// ---- output layout (float count offsets) ----
#define OUT_Y   0
#define OUT_C   (B_*F_)                              // 65536
#define OUT_N   (OUT_C + B_*NH_*HD_*HD_)             // 67174400
#define OUT_M   (OUT_N + B_*NH_*HD_)                 // 67305472
#define OUT_CS  (OUT_M + B_*NH_)                     // 67305728

// ---- scratch (static device globals; no allocation) ----
__device__ float g_up[B_ * 2 * HID_];       // up-projection: x | z
__device__ float g_convact[B_ * HID_];      // silu(conv_x)
__device__ float g_q[B_ * HID_];
__device__ float g_k[B_ * HID_];            // UNSCALED k
__device__ float g_v[B_ * HID_];
__device__ float g_fp[B_ * NH_];
__device__ float g_ip[B_ * NH_];
__device__ float g_den[B_ * NH_];           // den + EPS
__device__ float g_nom[B_ * NH_ * HD_];
__device__ float g_h[B_ * HID_];

__device__ __forceinline__ float warpsum(float v) {
#pragma unroll
    for (int o = 16; o; o >>= 1) v += __shfl_down_sync(0xffffffffu, v, o);
    return v;
}

// ============================================================
// K0: zero g_up (needed for split-K atomics)
// ============================================================
__global__ void zero_up_kernel() {
    int t = blockIdx.x * 256 + threadIdx.x;   // grid 1024 -> 262144 exactly
    g_up[t] = 0.f;
}

// ============================================================
// Split-K GEMM: Cout(64 x N) += A(64 x K) * Bm(K x N), row-major.
// Co == nullptr -> write to g_up.
// grid: (N/64, K/KC), block 256 (16x16 threads, 4x4 micro-tile)
// ============================================================
__global__ void __launch_bounds__(256) gemm64_kernel(
        const float* __restrict__ A, const float* __restrict__ Bm,
        float* Co, int K, int N, int KC) {
    float* dst = Co ? Co : g_up;
    const int n0 = blockIdx.x * 64;
    const int k0 = blockIdx.y * KC;
    const int tid = threadIdx.x;
    const int tx = tid & 15, ty = tid >> 4;

    __shared__ float As[16][65];   // pad to kill store conflicts
    __shared__ float Bs[16][64];

    float acc[4][4] = {};

    for (int kt = 0; kt < KC; kt += 16) {
        __syncthreads();
#pragma unroll
        for (int i = 0; i < 4; i++) {
            int lin = tid + i * 256;
            int mm = lin >> 4, kk = lin & 15;
            As[kk][mm] = A[mm * K + k0 + kt + kk];
            int kk2 = lin >> 6, jj = lin & 63;
            Bs[kk2][jj] = Bm[(size_t)(k0 + kt + kk2) * N + n0 + jj];
        }
        __syncthreads();
#pragma unroll
        for (int kk = 0; kk < 16; kk++) {
            float4 b4 = *(const float4*)&Bs[kk][tx * 4];
            float a0 = As[kk][ty * 4 + 0];
            float a1 = As[kk][ty * 4 + 1];
            float a2 = As[kk][ty * 4 + 2];
            float a3 = As[kk][ty * 4 + 3];
            acc[0][0] += a0 * b4.x; acc[0][1] += a0 * b4.y; acc[0][2] += a0 * b4.z; acc[0][3] += a0 * b4.w;
            acc[1][0] += a1 * b4.x; acc[1][1] += a1 * b4.y; acc[1][2] += a1 * b4.z; acc[1][3] += a1 * b4.w;
            acc[2][0] += a2 * b4.x; acc[2][1] += a2 * b4.y; acc[2][2] += a2 * b4.z; acc[2][3] += a2 * b4.w;
            acc[3][0] += a3 * b4.x; acc[3][1] += a3 * b4.y; acc[3][2] += a3 * b4.z; acc[3][3] += a3 * b4.w;
        }
    }
#pragma unroll
    for (int i = 0; i < 4; i++) {
        float* crow = dst + (size_t)(ty * 4 + i) * N + n0 + tx * 4;
        atomicAdd(crow + 0, acc[i][0]);
        atomicAdd(crow + 1, acc[i][1]);
        atomicAdd(crow + 2, acc[i][2]);
        atomicAdd(crow + 3, acc[i][3]);
    }
}

// ============================================================
// K2a: conv_state_new (to out), conv_x, silu -> g_convact
// grid 512 x 256 = B*HID threads
// ============================================================
__global__ void conv_kernel(const float* __restrict__ cs_in,
                            const float* __restrict__ conv_w,
                            const float* __restrict__ conv_b,
                            float* __restrict__ out) {
    int t = blockIdx.x * 256 + threadIdx.x;   // = b*2048 + hch
    int b = t >> 11, hch = t & 2047;
    float xv = g_up[b * 4096 + hch];
    const float* csb = cs_in + (size_t)b * KS_ * HID_;
    float c0 = csb[1 * HID_ + hch];
    float c1 = csb[2 * HID_ + hch];
    float c2 = csb[3 * HID_ + hch];
    float* ocs = out + OUT_CS + (size_t)b * KS_ * HID_;
    ocs[0 * HID_ + hch] = c0;
    ocs[1 * HID_ + hch] = c1;
    ocs[2 * HID_ + hch] = c2;
    ocs[3 * HID_ + hch] = xv;
    float s = c0 * conv_w[0 * HID_ + hch] + c1 * conv_w[1 * HID_ + hch]
            + c2 * conv_w[2 * HID_ + hch] + xv * conv_w[3 * HID_ + hch]
            + conv_b[hch];
    g_convact[t] = s / (1.f + expf(-s));      // silu
}

// ============================================================
// K2b: block-diagonal q,k,v (BS=4 blocks)
// ============================================================
__global__ void qkv_kernel(const float* __restrict__ Wq,
                           const float* __restrict__ Wk,
                           const float* __restrict__ Wv) {
    int t = blockIdx.x * 256 + threadIdx.x;   // = b*2048 + hch
    int b = t >> 11, hch = t & 2047;
    int nb = hch >> 2, e = hch & 3;
    const float* act = &g_convact[b * 2048 + (nb << 2)];
    const float* xr  = &g_up[b * 4096 + (nb << 2)];
    float q = 0.f, k = 0.f, v = 0.f;
#pragma unroll
    for (int d = 0; d < 4; d++) {
        float wq = Wq[nb * 16 + d * 4 + e];
        float wk = Wk[nb * 16 + d * 4 + e];
        float wv = Wv[nb * 16 + d * 4 + e];
        q += act[d] * wq;
        k += act[d] * wk;
        v += xr[d]  * wv;
    }
    g_q[t] = q; g_k[t] = k; g_v[t] = v;
}

// ============================================================
// K3: per-(b,h) gates, n_new (to out), den, m_new (to out);
//     also zeroes g_nom for this (b,h).
// grid 256 blocks x 256 threads
// ============================================================
__global__ void __launch_bounds__(256) gates_kernel(
        const float* __restrict__ nst, const float* __restrict__ mst,
        const float* __restrict__ Wi, const float* __restrict__ bi,
        const float* __restrict__ Wf, const float* __restrict__ bf,
        float* __restrict__ out) {
    int bh = blockIdx.x;
    int b = bh >> 2, h = bh & 3;
    int tid = threadIdx.x;
    int lane = tid & 31, wid = tid >> 5;

    // ---- reduce i_tilde, f_tilde over qkv (6144) ----
    float ai = 0.f, af = 0.f;
    for (int j = tid; j < 3 * HID_; j += 256) {
        float qkv;
        if (j < 2048)       qkv = g_q[b * 2048 + j];
        else if (j < 4096)  qkv = g_k[b * 2048 + j - 2048];
        else                qkv = g_v[b * 2048 + j - 4096];
        ai += qkv * Wi[j * NH_ + h];
        af += qkv * Wf[j * NH_ + h];
    }
    ai = warpsum(ai); af = warpsum(af);
    __shared__ float r1[8], r2[8], sc[3];
    if (lane == 0) { r1[wid] = ai; r2[wid] = af; }
    __syncthreads();
    if (tid < 32) {
        float a = (tid < 8) ? r1[tid] : 0.f;
        float f = (tid < 8) ? r2[tid] : 0.f;
        a = warpsum(a); f = warpsum(f);
        if (tid == 0) {
            float it = a + bi[h];
            float ft = f + bf[h];
            // log_f = -softplus(-ft), numerically stable
            float logf_ = -(fmaxf(-ft, 0.f) + log1pf(expf(-fabsf(ft))));
            float mold = mst[bh];
            float mnew = fmaxf(logf_ + mold, it);
            float ip = expf(it - mnew);
            float fp = expf(logf_ + mold - mnew);
            out[OUT_M + bh] = mnew;
            g_fp[bh] = fp; g_ip[bh] = ip;
            sc[0] = fp; sc[1] = ip; sc[2] = mnew;
        }
    }
    __syncthreads();
    float fp = sc[0], ip = sc[1], mnew = sc[2];

    // ---- n_new + q.n_new reduction; zero nom scratch ----
    float dacc = 0.f;
    for (int d = tid; d < HD_; d += 256) {
        int gi = b * 2048 + h * 512 + d;
        float kh = g_k[gi] * KSC;
        float nn = fp * nst[bh * 512 + d] + ip * kh;
        out[OUT_N + bh * 512 + d] = nn;
        dacc += g_q[gi] * nn;
        g_nom[bh * 512 + d] = 0.f;
    }
    dacc = warpsum(dacc);
    __syncthreads();
    if (lane == 0) r1[wid] = dacc;
    __syncthreads();
    if (tid == 0) {
        float s = 0.f;
#pragma unroll
        for (int w = 0; w < 8; w++) s += r1[w];
        float den = fmaxf(fabsf(s), expf(-mnew)) + EPS_;
        g_den[bh] = den;
    }
}

// ============================================================
// K4: C_new = fp*C + ip*kh (x) vh  (536 MB traffic) fused with
//     nom = q^T C_new (register accumulate + atomic reduce).
// grid (4, 256), block 256: ty in {0,1} splits 64 d-rows each,
// tx in [0,128) owns 4 consecutive e (float4).
// ============================================================
__global__ void __launch_bounds__(256) cupdate_kernel(
        const float* __restrict__ Cin, float* __restrict__ out) {
    int bh = blockIdx.y;
    int b = bh >> 2, h = bh & 3;
    int tid = threadIdx.x;
    int ty = tid >> 7;
    int tx = tid & 127;
    int e0 = tx * 4;
    int d0 = blockIdx.x * 128 + ty * 64;

    float fp = g_fp[bh], ip = g_ip[bh];

    __shared__ float sa[2][64], sq[2][64];
    if (tx < 64) {
        int gd = b * 2048 + h * 512 + d0 + tx;
        sa[ty][tx] = ip * KSC * g_k[gd];   // i_p * kh[d]
        sq[ty][tx] = g_q[gd];
    }
    __syncthreads();

    float4 vh = *(const float4*)&g_v[b * 2048 + h * 512 + e0];

    const float* cbase = Cin + ((size_t)bh * 512 + d0) * 512 + e0;
    float* obase = out + OUT_C + ((size_t)bh * 512 + d0) * 512 + e0;

    float4 nom = make_float4(0.f, 0.f, 0.f, 0.f);
#pragma unroll 8
    for (int dd = 0; dd < 64; dd++) {
        float a  = sa[ty][dd];
        float qd = sq[ty][dd];
        float4 c = *(const float4*)(cbase + (size_t)dd * 512);
        float4 cn;
        cn.x = fp * c.x + a * vh.x;
        cn.y = fp * c.y + a * vh.y;
        cn.z = fp * c.z + a * vh.z;
        cn.w = fp * c.w + a * vh.w;
        *(float4*)(obase + (size_t)dd * 512) = cn;
        nom.x += qd * cn.x;
        nom.y += qd * cn.y;
        nom.z += qd * cn.z;
        nom.w += qd * cn.w;
    }
    float* np = &g_nom[bh * 512 + e0];
    atomicAdd(np + 0, nom.x);
    atomicAdd(np + 1, nom.y);
    atomicAdd(np + 2, nom.z);
    atomicAdd(np + 3, nom.w);
}

// ============================================================
// K5: per-(b,h): h_tilde = nom/den, layernorm, skip, silu(z) gate.
//     Also zeroes the y output region (for down-GEMM atomics).
// grid 256 x 256
// ============================================================
__global__ void __launch_bounds__(256) finalize_kernel(
        const float* __restrict__ norm_scale, const float* __restrict__ skip,
        float* __restrict__ out) {
    int bh = blockIdx.x;
    int b = bh >> 2, h = bh & 3;
    int tid = threadIdx.x;
    int lane = tid & 31, wid = tid >> 5;

    out[OUT_Y + bh * 256 + tid] = 0.f;   // 256*256 == 65536 == |y|

    float den = g_den[bh];
    float v0 = g_nom[bh * 512 + tid] / den;
    float v1 = g_nom[bh * 512 + tid + 256] / den;

    float s = v0 + v1;
    float ss = v0 * v0 + v1 * v1;
    s = warpsum(s); ss = warpsum(ss);
    __shared__ float r1[8], r2[8], st[2];
    if (lane == 0) { r1[wid] = s; r2[wid] = ss; }
    __syncthreads();
    if (tid == 0) {
        float ts = 0.f, tss = 0.f;
#pragma unroll
        for (int w = 0; w < 8; w++) { ts += r1[w]; tss += r2[w]; }
        float mu = ts / 512.f;
        float var = tss / 512.f - mu * mu;
        st[0] = mu;
        st[1] = rsqrtf(var + EPS_);
    }
    __syncthreads();
    float mu = st[0], rstd = st[1];

#pragma unroll
    for (int i = 0; i < 2; i++) {
        int e = tid + i * 256;
        int hid = h * 512 + e;
        float v = (i == 0) ? v0 : v1;
        float hn = (v - mu) * rstd * norm_scale[h * 512 + e];
        float hv = hn + skip[hid] * g_convact[b * 2048 + hid];
        float z = g_up[b * 4096 + 2048 + hid];
        float sz = z / (1.f + expf(-z));
        g_h[b * 2048 + hid] = hv * sz;
    }
}

// ============================================================
// K6: y = g_h @ W_down, split-K with atomics into out[OUT_Y]
// ============================================================
__global__ void __launch_bounds__(256) gemm_down_kernel(
        const float* __restrict__ Wd, float* __restrict__ out, int KC) {
    const float* A = g_h;
    const int K = HID_, N = F_;
    const int n0 = blockIdx.x * 64;
    const int k0 = blockIdx.y * KC;
    const int tid = threadIdx.x;
    const int tx = tid & 15, ty = tid >> 4;
    __shared__ float As[16][65];
    __shared__ float Bs[16][64];
    float acc[4][4] = {};
    for (int kt = 0; kt < KC; kt += 16) {
        __syncthreads();
#pragma unroll
        for (int i = 0; i < 4; i++) {
            int lin = tid + i * 256;
            int mm = lin >> 4, kk = lin & 15;
            As[kk][mm] = A[mm * K + k0 + kt + kk];
            int kk2 = lin >> 6, jj = lin & 63;
            Bs[kk2][jj] = Wd[(size_t)(k0 + kt + kk2) * N + n0 + jj];
        }
        __syncthreads();
#pragma unroll
        for (int kk = 0; kk < 16; kk++) {
            float4 b4 = *(const float4*)&Bs[kk][tx * 4];
            float a0 = As[kk][ty * 4 + 0];
            float a1 = As[kk][ty * 4 + 1];
            float a2 = As[kk][ty * 4 + 2];
            float a3 = As[kk][ty * 4 + 3];
            acc[0][0] += a0 * b4.x; acc[0][1] += a0 * b4.y; acc[0][2] += a0 * b4.z; acc[0][3] += a0 * b4.w;
            acc[1][0] += a1 * b4.x; acc[1][1] += a1 * b4.y; acc[1][2] += a1 * b4.z; acc[1][3] += a1 * b4.w;
            acc[2][0] += a2 * b4.x; acc[2][1] += a2 * b4.y; acc[2][2] += a2 * b4.z; acc[2][3] += a2 * b4.w;
            acc[3][0] += a3 * b4.x; acc[3][1] += a3 * b4.y; acc[3][2] += a3 * b4.z; acc[3][3] += a3 * b4.w;
        }
    }
#pragma unroll
    for (int i = 0; i < 4; i++) {
        float* crow = out + OUT_Y + (size_t)(ty * 4 + i) * N + n0 + tx * 4;
        atomicAdd(crow + 0, acc[i][0]);
        atomicAdd(crow + 1, acc[i][1]);
        atomicAdd(crow + 2, acc[i][2]);
        atomicAdd(crow + 3, acc[i][3]);
    }
}

extern "C" void kernel_launch(void* const* d_in, const int* in_sizes, int n_in,
                              void* d_out, int out_size) {
    const float* inputs     = (const float*)d_in[0];
    const float* C          = (const float*)d_in[1];
    const float* n_state    = (const float*)d_in[2];
    const float* m_state    = (const float*)d_in[3];
    const float* conv_state = (const float*)d_in[4];
    const float* W_up       = (const float*)d_in[5];
    const float* conv_w     = (const float*)d_in[6];
    const float* conv_b     = (const float*)d_in[7];
    const float* Wq         = (const float*)d_in[8];
    const float* Wk         = (const float*)d_in[9];
    const float* Wv         = (const float*)d_in[10];
    const float* Wi         = (const float*)d_in[11];
    const float* bi         = (const float*)d_in[12];
    const float* Wf         = (const float*)d_in[13];
    const float* bf         = (const float*)d_in[14];
    const float* norm_scale = (const float*)d_in[15];
    const float* skip       = (const float*)d_in[16];
    const float* W_down     = (const float*)d_in[17];
    float* out = (float*)d_out;

    // K0: zero g_up for split-K atomics
    zero_up_kernel<<<1024, 256>>>();

    // K1: up = inputs @ W_up  (64x1024x4096), split-K=4
    gemm64_kernel<<<dim3(64, 4), 256>>>(inputs, W_up, nullptr, F_, 2 * HID_, 256);

    // K2a: conv + silu, conv_state_new
    conv_kernel<<<512, 256>>>(conv_state, conv_w, conv_b, out);

    // K2b: block-diagonal q,k,v
    qkv_kernel<<<512, 256>>>(Wq, Wk, Wv);

    // K3: gates, n_new, den, m_new; zero nom
    gates_kernel<<<256, 256>>>(n_state, m_state, Wi, bi, Wf, bf, out);

    // K4: C update fused with q^T C_new
    cupdate_kernel<<<dim3(4, 256), 256>>>(C, out);

    // K5: layernorm epilogue, gate with silu(z); zero y
    finalize_kernel<<<256, 256>>>(norm_scale, skip, out);

    // K6: y = h @ W_down  (64x2048x1024), split-K=8
    gemm_down_kernel<<<dim3(16, 8), 256>>>(W_down, out, 256);
}